// round 1
// baseline (speedup 1.0000x reference)
#include <cuda_runtime.h>

#define NCLS    4
#define MAXV    512
#define NROW    2048          // feat anchors
#define NANCH   4096
#define DIMF    128
#define NPIX    262144        // B*V*D*H*W = 2*1*32*64*64
#define PERBV   131072        // D*H*W
#define QSZ     5000
#define NBIN    16384
#define CANDMAX 4096

// ---------------- device scratch (no allocations allowed) ----------------
__device__ int                g_hist[NCLS * NBIN];
__device__ int                g_T[NCLS];
__device__ int                g_candCnt[NCLS];
__device__ unsigned long long g_cand[NCLS][CANDMAX];
__device__ int                g_selPix[NCLS][MAXV];
__device__ int                g_selQ[NCLS][MAXV];
__device__ float              g_Xa[NANCH * DIMF];      // anchors [4096,128]
__device__ float              g_C[NANCH * NANCH];      // raw dot products (64MB)
__device__ float              g_rowloss[NANCH];

// ---------------- helpers ----------------
__device__ __forceinline__ int score_bin(float s) {
    int b = (int)(s * 16384.0f);
    b = b < 0 ? 0 : b;
    return b > NBIN - 1 ? NBIN - 1 : b;
}

// ---------------- kernels ----------------
__global__ void k_zero() {
    int i = blockIdx.x * blockDim.x + threadIdx.x;
    if (i < NCLS * NBIN) g_hist[i] = 0;
    if (i < NCLS) g_candCnt[i] = 0;
}

__global__ void k_hist(const int* __restrict__ labels, const float* __restrict__ scores) {
    int i = blockIdx.x * blockDim.x + threadIdx.x;
    if (i >= NPIX) return;
    atomicAdd(&g_hist[labels[i] * NBIN + score_bin(scores[i])], 1);
}

__global__ void k_thresh() {
    int c = threadIdx.x;
    if (c >= NCLS) return;
    int cum = 0, b;
    for (b = NBIN - 1; b > 0; --b) {
        int h = g_hist[c * NBIN + b];
        if (cum + h >= MAXV) break;   // bin b is the cut bin
        cum += h;
    }
    g_T[c] = b;
}

__global__ void k_compact(const int* __restrict__ labels, const float* __restrict__ scores) {
    int i = blockIdx.x * blockDim.x + threadIdx.x;
    if (i >= NPIX) return;
    int c = labels[i];
    float s = scores[i];
    if (score_bin(s) >= g_T[c]) {
        int pos = atomicAdd(&g_candCnt[c], 1);
        if (pos < CANDMAX) {
            // monotone key: float bits (positive floats) high, lower index wins ties
            g_cand[c][pos] = ((unsigned long long)__float_as_uint(s) << 32)
                           | (unsigned int)(~(unsigned int)i);
        }
    }
}

__global__ void k_ranksel() {
    __shared__ unsigned long long sk[CANDMAX];
    int c = blockIdx.x;
    int n = g_candCnt[c];
    if (n > CANDMAX) n = CANDMAX;
    for (int i = threadIdx.x; i < n; i += blockDim.x) sk[i] = g_cand[c][i];
    __syncthreads();
    for (int i = threadIdx.x; i < n; i += blockDim.x) {
        unsigned long long k = sk[i];
        int rank = 0;
        for (int j = 0; j < n; ++j) rank += (sk[j] > k);
        if (rank < MAXV)
            g_selPix[c][rank] = (int)(~(unsigned int)(k & 0xFFFFFFFFull));
    }
}

__global__ void k_qsel(const float* __restrict__ qs_g) {
    __shared__ float qs[QSZ];
    int c = blockIdx.y;
    for (int j = threadIdx.x; j < QSZ; j += blockDim.x) qs[j] = qs_g[c * QSZ + j];
    __syncthreads();
    int base = blockIdx.x * 640;
    for (int i = base + threadIdx.x; i < base + 640 && i < QSZ; i += blockDim.x) {
        float si = qs[i];
        int rank = 0;
        for (int j = 0; j < QSZ; ++j) {
            float sj = qs[j];
            rank += (sj > si) || (sj == si && j < i);
        }
        if (rank < MAXV) g_selQ[c][rank] = i;
    }
}

__global__ void k_gather(const float* __restrict__ feats, const float* __restrict__ pq) {
    int r = blockIdx.x;
    int k = threadIdx.x;   // 0..127
    float v;
    if (r < NROW) {
        int c = r >> 9, slot = r & 511;
        int p  = g_selPix[c][slot];
        int bv = p >> 17;                 // / PERBV
        int off = p & (PERBV - 1);
        v = feats[(size_t)bv * DIMF * PERBV + (size_t)k * PERBV + off];
    } else {
        int rr = r - NROW;
        int c = rr >> 9, slot = rr & 511;
        int q = g_selQ[c][slot];
        v = pq[((size_t)c * QSZ + q) * DIMF + k];
    }
    g_Xa[r * DIMF + k] = v;
}

// C = Xa * Xa^T  (exploit symmetry: compute upper-triangular 128x128 blocks)
__global__ void __launch_bounds__(256) k_gemm() {
    int bi = blockIdx.y, bj = blockIdx.x;
    if (bj < bi) return;
    __shared__ float As[32][132];   // [k][i], stride 132 -> 16B aligned rows, conflict-lite
    __shared__ float Bs[32][132];
    int t  = threadIdx.x;
    int tx = t & 15, ty = t >> 4;
    float acc[8][8];
#pragma unroll
    for (int u = 0; u < 8; ++u)
#pragma unroll
        for (int v = 0; v < 8; ++v) acc[u][v] = 0.f;

    int lr = t >> 3;           // 0..31
    int lk = (t & 7) << 2;     // 0,4,...,28

    for (int k0 = 0; k0 < DIMF; k0 += 32) {
#pragma unroll
        for (int rr = 0; rr < 4; ++rr) {
            int r = lr + rr * 32;
            float4 va = *(const float4*)&g_Xa[(bi * 128 + r) * DIMF + k0 + lk];
            As[lk + 0][r] = va.x; As[lk + 1][r] = va.y;
            As[lk + 2][r] = va.z; As[lk + 3][r] = va.w;
            float4 vb = *(const float4*)&g_Xa[(bj * 128 + r) * DIMF + k0 + lk];
            Bs[lk + 0][r] = vb.x; Bs[lk + 1][r] = vb.y;
            Bs[lk + 2][r] = vb.z; Bs[lk + 3][r] = vb.w;
        }
        __syncthreads();
#pragma unroll
        for (int kk = 0; kk < 32; ++kk) {
            float ra[8], rb[8];
#pragma unroll
            for (int u = 0; u < 8; ++u) ra[u] = As[kk][ty * 8 + u];
#pragma unroll
            for (int v = 0; v < 8; ++v) rb[v] = Bs[kk][tx * 8 + v];
#pragma unroll
            for (int u = 0; u < 8; ++u)
#pragma unroll
                for (int v = 0; v < 8; ++v) acc[u][v] += ra[u] * rb[v];
        }
        __syncthreads();
    }

    int r0 = bi * 128 + ty * 8, c0 = bj * 128 + tx * 8;
#pragma unroll
    for (int u = 0; u < 8; ++u)
#pragma unroll
        for (int v = 0; v < 8; ++v) {
            float a = acc[u][v];
            g_C[(r0 + u) * NANCH + (c0 + v)] = a;
            if (bi != bj) g_C[(c0 + v) * NANCH + (r0 + u)] = a;
        }
}

// per-row: max -> neg-exp-sum -> positive log-prob sum -> row loss
__global__ void __launch_bounds__(256) k_epi() {
    __shared__ float red[256];
    int i  = blockIdx.x;
    int ci = (i & 2047) >> 9;
    const float* row = &g_C[(size_t)i * NANCH];
    int t = threadIdx.x;

    // pass 1: row max of raw dot (logit = 10*dot; 10>0 so max commutes)
    float m = -3.4e38f;
    for (int j = t; j < NANCH; j += 256) m = fmaxf(m, row[j]);
    red[t] = m; __syncthreads();
    for (int o = 128; o > 0; o >>= 1) { if (t < o) red[t] = fmaxf(red[t], red[t + o]); __syncthreads(); }
    float M = red[0] * 10.0f;
    __syncthreads();

    // pass 2: sum_{neg_mask} exp(l')   (neg = different class OR j==i)
    float ns = 0.f;
    for (int j = t; j < NANCH; j += 256) {
        int cj = (j & 2047) >> 9;
        if (cj != ci || j == i) ns += __expf(fmaf(row[j], 10.0f, -M));
    }
    red[t] = ns; __syncthreads();
    for (int o = 128; o > 0; o >>= 1) { if (t < o) red[t] += red[t + o]; __syncthreads(); }
    float NS = red[0];
    __syncthreads();

    // pass 3: sum over positives (same class, j!=i): l' - log(exp(l') + NS + 1e-10)
    float ps = 0.f;
    int base0 = ci * 512, base1 = NROW + ci * 512;
    for (int q = t; q < 1024; q += 256) {
        int j = (q < 512) ? (base0 + q) : (base1 + (q - 512));
        if (j != i) {
            float lp = fmaf(row[j], 10.0f, -M);
            ps += lp - __logf(__expf(lp) + NS + 1e-10f);
        }
    }
    red[t] = ps; __syncthreads();
    for (int o = 128; o > 0; o >>= 1) { if (t < o) red[t] += red[t + o]; __syncthreads(); }

    if (t == 0)
        g_rowloss[i] = -(0.1f / 0.07f) * red[0] / (1023.0f + 1e-10f);
}

__global__ void k_reduce(float* __restrict__ out) {
    __shared__ float sh[1024];
    int t = threadIdx.x;
    sh[t] = g_rowloss[t] + g_rowloss[t + 1024] + g_rowloss[t + 2048] + g_rowloss[t + 3072];
    __syncthreads();
    for (int o = 512; o > 0; o >>= 1) { if (t < o) sh[t] += sh[t + o]; __syncthreads(); }
    if (t == 0) out[0] = sh[0] / 4096.0f;
}

// ---------------- launch ----------------
extern "C" void kernel_launch(void* const* d_in, const int* in_sizes, int n_in,
                              void* d_out, int out_size) {
    const float* feats      = (const float*)d_in[0];   // [2,1,128,32,64,64]
    const int*   labels     = (const int*)  d_in[1];   // [2,32,64,64]
    const float* pixel_q    = (const float*)d_in[2];   // [4,5000,128]
    const float* pix_scores = (const float*)d_in[3];   // [262144]
    const float* q_scores   = (const float*)d_in[4];   // [4,5000]
    float* out = (float*)d_out;

    k_zero   <<<(NCLS * NBIN + 255) / 256, 256>>>();
    k_hist   <<<(NPIX + 255) / 256, 256>>>(labels, pix_scores);
    k_thresh <<<1, 32>>>();
    k_compact<<<(NPIX + 255) / 256, 256>>>(labels, pix_scores);
    k_ranksel<<<NCLS, 1024>>>();
    k_qsel   <<<dim3(8, NCLS), 256>>>(q_scores);
    k_gather <<<NANCH, DIMF>>>(feats, pixel_q);
    k_gemm   <<<dim3(32, 32), 256>>>();
    k_epi    <<<NANCH, 256>>>();
    k_reduce <<<1, 1024>>>(out);
}

// round 4
// speedup vs baseline: 1.6446x; 1.6446x over previous
#include <cuda_runtime.h>
#include <cuda_bf16.h>
#include <cstdint>

#define NCLS    4
#define MAXV    512
#define NROW    2048
#define NANCH   4096
#define DIMF    128
#define NPIX    262144
#define PERBV   131072
#define QSZ     5000
#define NBIN    16384
#define CANDMAX 4096
#define NSEL    8          // 0-3 pixel classes, 4-7 queue classes

// ---------------- device scratch ----------------
__device__ int                g_hist[NSEL * NBIN];
__device__ int                g_T[NSEL];
__device__ int                g_candCnt[NSEL];
__device__ unsigned long long g_cand[NSEL][CANDMAX];
__device__ int                g_sel[NSEL][MAXV];
__device__ __nv_bfloat16      g_Xhi[NANCH * DIMF];
__device__ __nv_bfloat16      g_Xlo[NANCH * DIMF];
__device__ float              g_pm[32][NANCH];      // per (coltile, row): rowmax*10
__device__ float              g_ps[32][NANCH];      // per (coltile, row): sum exp
__device__ float              g_pos[NANCH * 1024];  // raw positive dots
__device__ float              g_rowloss[NANCH];

// ---------------- helpers ----------------
__device__ __forceinline__ uint32_t smem_u32(const void* p) {
    uint32_t a;
    asm("{ .reg .u64 t; cvta.to.shared.u64 t, %1; cvt.u32.u64 %0, t; }" : "=r"(a) : "l"(p));
    return a;
}
__device__ __forceinline__ void ldsm4(uint32_t* r, uint32_t addr) {
    asm volatile("ldmatrix.sync.aligned.m8n8.x4.shared.b16 {%0,%1,%2,%3}, [%4];"
                 : "=r"(r[0]), "=r"(r[1]), "=r"(r[2]), "=r"(r[3]) : "r"(addr));
}
__device__ __forceinline__ void mma_bf16(float* c, const uint32_t* a, uint32_t b0, uint32_t b1) {
    asm volatile("mma.sync.aligned.m16n8k16.row.col.f32.bf16.bf16.f32 "
                 "{%0,%1,%2,%3}, {%4,%5,%6,%7}, {%8,%9}, {%0,%1,%2,%3};"
                 : "+f"(c[0]), "+f"(c[1]), "+f"(c[2]), "+f"(c[3])
                 : "r"(a[0]), "r"(a[1]), "r"(a[2]), "r"(a[3]), "r"(b0), "r"(b1));
}
__device__ __forceinline__ int score_bin(float s) {
    int b = (int)(s * 16384.0f);
    b = b < 0 ? 0 : b;
    return b > NBIN - 1 ? NBIN - 1 : b;
}

// ---------------- selection ----------------
__global__ void k_zero() {
    int i = blockIdx.x * blockDim.x + threadIdx.x;
    if (i < NSEL * NBIN) g_hist[i] = 0;
    if (i < NSEL) g_candCnt[i] = 0;
}

__global__ void k_hist(const int* __restrict__ labels, const float* __restrict__ scores) {
    int i = blockIdx.x * blockDim.x + threadIdx.x;
    if (i >= NPIX) return;
    atomicAdd(&g_hist[labels[i] * NBIN + score_bin(scores[i])], 1);
}

__global__ void k_qhist(const float* __restrict__ qs) {
    int i = blockIdx.x * blockDim.x + threadIdx.x;
    if (i >= NCLS * QSZ) return;
    atomicAdd(&g_hist[(4 + i / QSZ) * NBIN + score_bin(qs[i])], 1);
}

__global__ void k_thresh() {
    int c = threadIdx.x;
    if (c >= NSEL) return;
    int cum = 0, b;
    for (b = NBIN - 1; b > 0; --b) {
        int h = g_hist[c * NBIN + b];
        if (cum + h >= MAXV) break;
        cum += h;
    }
    g_T[c] = b;
}

__global__ void k_compact(const int* __restrict__ labels, const float* __restrict__ scores) {
    int i = blockIdx.x * blockDim.x + threadIdx.x;
    if (i >= NPIX) return;
    int c = labels[i];
    float s = scores[i];
    if (score_bin(s) >= g_T[c]) {
        int pos = atomicAdd(&g_candCnt[c], 1);
        if (pos < CANDMAX)
            g_cand[c][pos] = ((unsigned long long)__float_as_uint(s) << 32)
                           | (unsigned int)(~(unsigned int)i);
    }
}

__global__ void k_qcompact(const float* __restrict__ qs) {
    int i = blockIdx.x * blockDim.x + threadIdx.x;
    if (i >= NCLS * QSZ) return;
    int c = 4 + i / QSZ;
    int id = i % QSZ;
    float s = qs[i];
    if (score_bin(s) >= g_T[c]) {
        int pos = atomicAdd(&g_candCnt[c], 1);
        if (pos < CANDMAX)
            g_cand[c][pos] = ((unsigned long long)__float_as_uint(s) << 32)
                           | (unsigned int)(~(unsigned int)id);
    }
}

__global__ void k_ranksel() {
    __shared__ unsigned long long sk[CANDMAX];
    int c = blockIdx.x;
    int n = g_candCnt[c];
    if (n > CANDMAX) n = CANDMAX;
    for (int i = threadIdx.x; i < n; i += blockDim.x) sk[i] = g_cand[c][i];
    __syncthreads();
    for (int i = threadIdx.x; i < n; i += blockDim.x) {
        unsigned long long k = sk[i];
        int rank = 0;
        for (int j = 0; j < n; ++j) rank += (sk[j] > k);
        if (rank < MAXV)
            g_sel[c][rank] = (int)(~(unsigned int)(k & 0xFFFFFFFFull));
    }
}

// ---------------- gather + split to bf16 hi/lo ----------------
__global__ void k_gather(const float* __restrict__ feats, const float* __restrict__ pq) {
    int r = blockIdx.x;
    int k = threadIdx.x;   // 0..127
    float v;
    if (r < NROW) {
        int c = r >> 9, slot = r & 511;
        int p  = g_sel[c][slot];
        int bv = p >> 17;
        int off = p & (PERBV - 1);
        v = feats[(size_t)bv * DIMF * PERBV + (size_t)k * PERBV + off];
    } else {
        int rr = r - NROW;
        int c = rr >> 9, slot = rr & 511;
        int q = g_sel[4 + c][slot];
        v = pq[((size_t)c * QSZ + q) * DIMF + k];
    }
    __nv_bfloat16 hi = __float2bfloat16(v);
    __nv_bfloat16 lo = __float2bfloat16(v - __bfloat162float(hi));
    g_Xhi[r * DIMF + k] = hi;
    g_Xlo[r * DIMF + k] = lo;
}

// ---------------- fused mma.sync GEMM + softmax partials ----------------
// Block (bi, bj): C_tile[128x128] = X[bi*128..][:] . X[bj*128..][:]^T via
// split-bf16 (hi*hi + hi*lo + lo*hi). Emits per-(coltile,row) max & sum-exp
// partials; same-class tiles dump raw dots to g_pos.
// SMEM: Ahi | Alo | Bhi | Blo, each 128 rows x 256B, chunk-XOR swizzled.
#define SMEM_DYN (4 * 32768)
__global__ void __launch_bounds__(256, 1) k_gemm() {
    extern __shared__ char dsm[];
    __shared__ float sP[4][128];
    __shared__ float sM[128];
    int t = threadIdx.x, lane = t & 31, w = t >> 5;
    int wm = w & 1, wn = w >> 1;               // warp tile 64(m) x 32(n)
    int gID = lane >> 2, tig = lane & 3;
    int bi = blockIdx.y, bj = blockIdx.x;
    uint32_t sbase = smem_u32(dsm);

    // ---- load 4 tiles to swizzled smem ----
    const __nv_bfloat16* srcs[4] = {
        g_Xhi + (size_t)bi * 128 * DIMF, g_Xlo + (size_t)bi * 128 * DIMF,
        g_Xhi + (size_t)bj * 128 * DIMF, g_Xlo + (size_t)bj * 128 * DIMF };
#pragma unroll
    for (int tl = 0; tl < 4; ++tl) {
        const uint4* src = (const uint4*)srcs[tl];
        char* dst = dsm + tl * 32768;
#pragma unroll
        for (int it = 0; it < 8; ++it) {
            int idx = t + it * 256;            // 2048 chunks of 16B
            int row = idx >> 4, ch = idx & 15;
            uint4 v = src[idx];
            *(uint4*)(dst + row * 256 + ((ch ^ (row & 7)) << 4)) = v;
        }
    }
    __syncthreads();

    // ---- mma mainloop ----
    float c[4][4][4];
#pragma unroll
    for (int mf = 0; mf < 4; ++mf)
#pragma unroll
        for (int nf = 0; nf < 4; ++nf)
#pragma unroll
            for (int u = 0; u < 4; ++u) c[mf][nf][u] = 0.f;

    int q = lane >> 3, rowin = lane & 7;
    // A lane address components: row = m0 + rowin + (q&1)*8, chunk = 2k + (q>>1)
    // B lane address components: row = n0 + rowin + (q>>1)*8, chunk = 2k + (q&1)
    int rA_in = rowin + (q & 1) * 8;
    int rB_in = rowin + (q >> 1) * 8;
    int cA_add = q >> 1, cB_add = q & 1;

#pragma unroll
    for (int term = 0; term < 3; ++term) {
        uint32_t Ab = sbase + (term == 2 ? 32768 : 0);
        uint32_t Bb = sbase + (term == 1 ? 98304 : 65536);
#pragma unroll
        for (int k0 = 0; k0 < 8; ++k0) {
            uint32_t a[4][4];
#pragma unroll
            for (int mf = 0; mf < 4; ++mf) {
                int row = wm * 64 + mf * 16 + rA_in;
                int ch = 2 * k0 + cA_add;
                ldsm4(a[mf], Ab + row * 256 + ((ch ^ (row & 7)) << 4));
            }
            uint32_t b[2][4];
#pragma unroll
            for (int nf2 = 0; nf2 < 2; ++nf2) {
                int row = wn * 32 + nf2 * 16 + rB_in;
                int ch = 2 * k0 + cB_add;
                ldsm4(b[nf2], Bb + row * 256 + ((ch ^ (row & 7)) << 4));
            }
#pragma unroll
            for (int mf = 0; mf < 4; ++mf)
#pragma unroll
                for (int nf = 0; nf < 4; ++nf)
                    mma_bf16(c[mf][nf], a[mf], b[nf >> 1][(nf & 1) * 2], b[nf >> 1][(nf & 1) * 2 + 1]);
        }
    }

    // ---- positive-tile raw dot dump ----
    int rc = (bi < 16) ? (bi >> 2) : ((bi - 16) >> 2);
    int cc = (bj < 16) ? (bj >> 2) : ((bj - 16) >> 2);
    if (rc == cc) {
        int pidx = (bj < 16) ? (bj & 3) : (4 + ((bj - 16) & 3));
#pragma unroll
        for (int mf = 0; mf < 4; ++mf)
#pragma unroll
            for (int rs = 0; rs < 2; ++rs) {
                int row = bi * 128 + wm * 64 + mf * 16 + gID + rs * 8;
                float* dst = g_pos + (size_t)row * 1024 + pidx * 128;
#pragma unroll
                for (int nf = 0; nf < 4; ++nf) {
                    int col = wn * 32 + nf * 8 + 2 * tig;
                    *(float2*)(dst + col) = make_float2(c[mf][nf][2 * rs], c[mf][nf][2 * rs + 1]);
                }
            }
    }

    // ---- per-row max over this 128-col tile ----
#pragma unroll
    for (int mf = 0; mf < 4; ++mf)
#pragma unroll
        for (int rs = 0; rs < 2; ++rs) {
            int rl = wm * 64 + mf * 16 + gID + rs * 8;
            float mx = -3.4e38f;
#pragma unroll
            for (int nf = 0; nf < 4; ++nf)
                mx = fmaxf(mx, fmaxf(c[mf][nf][2 * rs], c[mf][nf][2 * rs + 1]));
            mx = fmaxf(mx, __shfl_xor_sync(0xffffffffu, mx, 1));
            mx = fmaxf(mx, __shfl_xor_sync(0xffffffffu, mx, 2));
            if (tig == 0) sP[wn][rl] = mx;
        }
    __syncthreads();
    if (t < 128) sM[t] = fmaxf(fmaxf(sP[0][t], sP[1][t]), fmaxf(sP[2][t], sP[3][t]));
    __syncthreads();

    // ---- per-row sum of exp((dot - max)*10) ----
#pragma unroll
    for (int mf = 0; mf < 4; ++mf)
#pragma unroll
        for (int rs = 0; rs < 2; ++rs) {
            int rl = wm * 64 + mf * 16 + gID + rs * 8;
            float M10 = sM[rl] * 10.0f;
            float s = 0.f;
#pragma unroll
            for (int nf = 0; nf < 4; ++nf)
                s += __expf(fmaf(c[mf][nf][2 * rs], 10.0f, -M10))
                   + __expf(fmaf(c[mf][nf][2 * rs + 1], 10.0f, -M10));
            s += __shfl_xor_sync(0xffffffffu, s, 1);
            s += __shfl_xor_sync(0xffffffffu, s, 2);
            if (tig == 0) sP[wn][rl] = s;
        }
    __syncthreads();
    if (t < 128) {
        g_pm[bj][bi * 128 + t] = sM[t] * 10.0f;
        g_ps[bj][bi * 128 + t] = sP[0][t] + sP[1][t] + sP[2][t] + sP[3][t];
    }
}

// ---------------- final per-row loss ----------------
__global__ void __launch_bounds__(128) k_loss() {
    __shared__ float red[128];
    int i = blockIdx.x, t = threadIdx.x;
    int c = (i < NROW) ? (i >> 9) : ((i - NROW) >> 9);

    red[t] = (t < 32) ? g_pm[t][i] : -3.4e38f;
    __syncthreads();
    for (int o = 64; o > 0; o >>= 1) { if (t < o) red[t] = fmaxf(red[t], red[t + o]); __syncthreads(); }
    float M = red[0];
    __syncthreads();

    red[t] = (t < 32) ? g_ps[t][i] * __expf(g_pm[t][i] - M) : 0.f;
    __syncthreads();
    for (int o = 64; o > 0; o >>= 1) { if (t < o) red[t] += red[t + o]; __syncthreads(); }
    float S_all = red[0];
    __syncthreads();

    float lp[8]; int jj[8];
    float sp = 0.f;
#pragma unroll
    for (int u = 0; u < 8; ++u) {
        int qq = t + u * 128;
        int j = (qq < 512) ? c * 512 + qq : NROW + c * 512 + (qq - 512);
        jj[u] = j;
        float d = g_pos[(size_t)i * 1024 + qq];
        lp[u] = fmaf(d, 10.0f, -M);
        if (j != i) sp += __expf(lp[u]);
    }
    red[t] = sp;
    __syncthreads();
    for (int o = 64; o > 0; o >>= 1) { if (t < o) red[t] += red[t + o]; __syncthreads(); }
    float NS = S_all - red[0];
    __syncthreads();

    float ps = 0.f;
#pragma unroll
    for (int u = 0; u < 8; ++u)
        if (jj[u] != i)
            ps += lp[u] - __logf(__expf(lp[u]) + NS + 1e-10f);
    red[t] = ps;
    __syncthreads();
    for (int o = 64; o > 0; o >>= 1) { if (t < o) red[t] += red[t + o]; __syncthreads(); }

    if (t == 0)
        g_rowloss[i] = -(0.1f / 0.07f) * red[0] / (1023.0f + 1e-10f);
}

__global__ void k_reduce(float* __restrict__ out) {
    __shared__ float sh[1024];
    int t = threadIdx.x;
    sh[t] = g_rowloss[t] + g_rowloss[t + 1024] + g_rowloss[t + 2048] + g_rowloss[t + 3072];
    __syncthreads();
    for (int o = 512; o > 0; o >>= 1) { if (t < o) sh[t] += sh[t + o]; __syncthreads(); }
    if (t == 0) out[0] = sh[0] / 4096.0f;
}

// ---------------- launch ----------------
extern "C" void kernel_launch(void* const* d_in, const int* in_sizes, int n_in,
                              void* d_out, int out_size) {
    const float* feats      = (const float*)d_in[0];
    const int*   labels     = (const int*)  d_in[1];
    const float* pixel_q    = (const float*)d_in[2];
    const float* pix_scores = (const float*)d_in[3];
    const float* q_scores   = (const float*)d_in[4];
    float* out = (float*)d_out;

    cudaFuncSetAttribute(k_gemm, cudaFuncAttributeMaxDynamicSharedMemorySize, SMEM_DYN);

    k_zero    <<<(NSEL * NBIN + 255) / 256, 256>>>();
    k_hist    <<<(NPIX + 255) / 256, 256>>>(labels, pix_scores);
    k_qhist   <<<(NCLS * QSZ + 255) / 256, 256>>>(q_scores);
    k_thresh  <<<1, 32>>>();
    k_compact <<<(NPIX + 255) / 256, 256>>>(labels, pix_scores);
    k_qcompact<<<(NCLS * QSZ + 255) / 256, 256>>>(q_scores);
    k_ranksel <<<NSEL, 1024>>>();
    k_gather  <<<NANCH, DIMF>>>(feats, pixel_q);
    k_gemm    <<<dim3(32, 32), 256, SMEM_DYN>>>();
    k_loss    <<<NANCH, 128>>>();
    k_reduce  <<<1, 1024>>>(out);
}

// round 5
// speedup vs baseline: 3.2750x; 1.9913x over previous
#include <cuda_runtime.h>
#include <cuda_bf16.h>
#include <cstdint>

#define NCLS    4
#define MAXV    512
#define NROW    2048
#define NANCH   4096
#define DIMF    128
#define NPIX    262144
#define PERBV   131072
#define QSZ     5000
#define NBIN    16384
#define CANDMAX 4096
#define NSEL    8          // 0-3 pixel classes, 4-7 queue classes

// ---------------- device scratch ----------------
__device__ int                g_hist[NSEL * NBIN];
__device__ int                g_T[NSEL];
__device__ int                g_candCnt[NSEL];
__device__ unsigned long long g_cand[NSEL][CANDMAX];
__device__ int                g_sel[NSEL][MAXV];
__device__ __nv_bfloat16      g_Xhi[NANCH * DIMF];
__device__ __nv_bfloat16      g_Xlo[NANCH * DIMF];
__device__ float              g_pm[32][NANCH];      // per (coltile, row): rowmax*10
__device__ float              g_ps[32][NANCH];      // per (coltile, row): sum exp
__device__ float              g_pos[NANCH * 1024];  // raw positive dots
__device__ float              g_rowloss[NANCH];

// ---------------- helpers ----------------
__device__ __forceinline__ uint32_t smem_u32(const void* p) {
    uint32_t a;
    asm("{ .reg .u64 t; cvta.to.shared.u64 t, %1; cvt.u32.u64 %0, t; }" : "=r"(a) : "l"(p));
    return a;
}
__device__ __forceinline__ void ldsm4(uint32_t* r, uint32_t addr) {
    asm volatile("ldmatrix.sync.aligned.m8n8.x4.shared.b16 {%0,%1,%2,%3}, [%4];"
                 : "=r"(r[0]), "=r"(r[1]), "=r"(r[2]), "=r"(r[3]) : "r"(addr));
}
__device__ __forceinline__ void mma_bf16(float* c, const uint32_t* a, uint32_t b0, uint32_t b1) {
    asm volatile("mma.sync.aligned.m16n8k16.row.col.f32.bf16.bf16.f32 "
                 "{%0,%1,%2,%3}, {%4,%5,%6,%7}, {%8,%9}, {%0,%1,%2,%3};"
                 : "+f"(c[0]), "+f"(c[1]), "+f"(c[2]), "+f"(c[3])
                 : "r"(a[0]), "r"(a[1]), "r"(a[2]), "r"(a[3]), "r"(b0), "r"(b1));
}
__device__ __forceinline__ int score_bin(float s) {
    int b = (int)(s * 16384.0f);
    b = b < 0 ? 0 : b;
    return b > NBIN - 1 ? NBIN - 1 : b;
}

// ---------------- selection ----------------
__global__ void k_zero() {
    int i = blockIdx.x * blockDim.x + threadIdx.x;
    if (i < NSEL * NBIN) g_hist[i] = 0;
    if (i < NSEL) { g_candCnt[i] = 0; g_T[i] = 0; }
}

__global__ void k_hist(const int* __restrict__ labels, const float* __restrict__ scores) {
    int i = blockIdx.x * blockDim.x + threadIdx.x;
    if (i >= NPIX) return;
    atomicAdd(&g_hist[labels[i] * NBIN + score_bin(scores[i])], 1);
}

__global__ void k_qhist(const float* __restrict__ qs) {
    int i = blockIdx.x * blockDim.x + threadIdx.x;
    if (i >= NCLS * QSZ) return;
    atomicAdd(&g_hist[(4 + i / QSZ) * NBIN + score_bin(qs[i])], 1);
}

// parallel threshold: per class, find largest bin b with suffix_inclusive(b) >= MAXV
#define TH_THREADS 512
#define TH_CH      (NBIN / TH_THREADS)   // 32 bins per thread
__global__ void __launch_bounds__(TH_THREADS) k_thresh() {
    __shared__ int csum[TH_THREADS];
    int c = blockIdx.x, t = threadIdx.x;
    int base = c * NBIN + t * TH_CH;
    int h[TH_CH];
    int s = 0;
#pragma unroll
    for (int u = 0; u < TH_CH; ++u) { h[u] = g_hist[base + u]; s += h[u]; }
    csum[t] = s;
    __syncthreads();
    // suffix-inclusive scan over chunk sums
    for (int o = 1; o < TH_THREADS; o <<= 1) {
        int v = (t + o < TH_THREADS) ? csum[t + o] : 0;
        __syncthreads();
        csum[t] += v;
        __syncthreads();
    }
    int above = (t + 1 < TH_THREADS) ? csum[t + 1] : 0;
    if (above < MAXV && csum[t] >= MAXV) {
        // boundary is inside this thread's chunk
        int running = above;
#pragma unroll
        for (int u = TH_CH - 1; u >= 0; --u) {
            running += h[u];
            if (running >= MAXV) { g_T[c] = t * TH_CH + u; break; }
        }
    }
}

__global__ void k_compact(const int* __restrict__ labels, const float* __restrict__ scores) {
    int i = blockIdx.x * blockDim.x + threadIdx.x;
    if (i >= NPIX) return;
    int c = labels[i];
    float s = scores[i];
    if (score_bin(s) >= g_T[c]) {
        int pos = atomicAdd(&g_candCnt[c], 1);
        if (pos < CANDMAX)
            g_cand[c][pos] = ((unsigned long long)__float_as_uint(s) << 32)
                           | (unsigned int)(~(unsigned int)i);
    }
}

__global__ void k_qcompact(const float* __restrict__ qs) {
    int i = blockIdx.x * blockDim.x + threadIdx.x;
    if (i >= NCLS * QSZ) return;
    int c = 4 + i / QSZ;
    int id = i % QSZ;
    float s = qs[i];
    if (score_bin(s) >= g_T[c]) {
        int pos = atomicAdd(&g_candCnt[c], 1);
        if (pos < CANDMAX)
            g_cand[c][pos] = ((unsigned long long)__float_as_uint(s) << 32)
                           | (unsigned int)(~(unsigned int)id);
    }
}

__global__ void k_ranksel() {
    __shared__ unsigned long long sk[CANDMAX];
    int c = blockIdx.x;
    int n = g_candCnt[c];
    if (n > CANDMAX) n = CANDMAX;
    for (int i = threadIdx.x; i < n; i += blockDim.x) sk[i] = g_cand[c][i];
    __syncthreads();
    for (int i = threadIdx.x; i < n; i += blockDim.x) {
        unsigned long long k = sk[i];
        int rank = 0;
        for (int j = 0; j < n; ++j) rank += (sk[j] > k);
        if (rank < MAXV)
            g_sel[c][rank] = (int)(~(unsigned int)(k & 0xFFFFFFFFull));
    }
}

// ---------------- gather + split to bf16 hi/lo ----------------
__global__ void k_gather(const float* __restrict__ feats, const float* __restrict__ pq) {
    int r = blockIdx.x;
    int k = threadIdx.x;   // 0..127
    float v;
    if (r < NROW) {
        int c = r >> 9, slot = r & 511;
        int p  = g_sel[c][slot];
        int bv = p >> 17;
        int off = p & (PERBV - 1);
        v = feats[(size_t)bv * DIMF * PERBV + (size_t)k * PERBV + off];
    } else {
        int rr = r - NROW;
        int c = rr >> 9, slot = rr & 511;
        int q = g_sel[4 + c][slot];
        v = pq[((size_t)c * QSZ + q) * DIMF + k];
    }
    __nv_bfloat16 hi = __float2bfloat16(v);
    __nv_bfloat16 lo = __float2bfloat16(v - __bfloat162float(hi));
    g_Xhi[r * DIMF + k] = hi;
    g_Xlo[r * DIMF + k] = lo;
}

// ---------------- fused mma.sync GEMM + softmax partials ----------------
#define SMEM_DYN (4 * 32768)
__global__ void __launch_bounds__(256, 1) k_gemm() {
    extern __shared__ char dsm[];
    __shared__ float sP[4][128];
    __shared__ float sM[128];
    int t = threadIdx.x, lane = t & 31, w = t >> 5;
    int wm = w & 1, wn = w >> 1;               // warp tile 64(m) x 32(n)
    int gID = lane >> 2, tig = lane & 3;
    int bi = blockIdx.y, bj = blockIdx.x;
    uint32_t sbase = smem_u32(dsm);

    // ---- load 4 tiles to swizzled smem ----
    const __nv_bfloat16* srcs[4] = {
        g_Xhi + (size_t)bi * 128 * DIMF, g_Xlo + (size_t)bi * 128 * DIMF,
        g_Xhi + (size_t)bj * 128 * DIMF, g_Xlo + (size_t)bj * 128 * DIMF };
#pragma unroll
    for (int tl = 0; tl < 4; ++tl) {
        const uint4* src = (const uint4*)srcs[tl];
        char* dst = dsm + tl * 32768;
#pragma unroll
        for (int it = 0; it < 8; ++it) {
            int idx = t + it * 256;            // 2048 chunks of 16B
            int row = idx >> 4, ch = idx & 15;
            uint4 v = src[idx];
            *(uint4*)(dst + row * 256 + ((ch ^ (row & 7)) << 4)) = v;
        }
    }
    __syncthreads();

    // ---- mma mainloop ----
    float c[4][4][4];
#pragma unroll
    for (int mf = 0; mf < 4; ++mf)
#pragma unroll
        for (int nf = 0; nf < 4; ++nf)
#pragma unroll
            for (int u = 0; u < 4; ++u) c[mf][nf][u] = 0.f;

    int q = lane >> 3, rowin = lane & 7;
    int rA_in = rowin + (q & 1) * 8;
    int rB_in = rowin + (q >> 1) * 8;
    int cA_add = q >> 1, cB_add = q & 1;

#pragma unroll
    for (int term = 0; term < 3; ++term) {
        uint32_t Ab = sbase + (term == 2 ? 32768 : 0);
        uint32_t Bb = sbase + (term == 1 ? 98304 : 65536);
#pragma unroll
        for (int k0 = 0; k0 < 8; ++k0) {
            uint32_t a[4][4];
#pragma unroll
            for (int mf = 0; mf < 4; ++mf) {
                int row = wm * 64 + mf * 16 + rA_in;
                int ch = 2 * k0 + cA_add;
                ldsm4(a[mf], Ab + row * 256 + ((ch ^ (row & 7)) << 4));
            }
            uint32_t b[2][4];
#pragma unroll
            for (int nf2 = 0; nf2 < 2; ++nf2) {
                int row = wn * 32 + nf2 * 16 + rB_in;
                int ch = 2 * k0 + cB_add;
                ldsm4(b[nf2], Bb + row * 256 + ((ch ^ (row & 7)) << 4));
            }
#pragma unroll
            for (int mf = 0; mf < 4; ++mf)
#pragma unroll
                for (int nf = 0; nf < 4; ++nf)
                    mma_bf16(c[mf][nf], a[mf], b[nf >> 1][(nf & 1) * 2], b[nf >> 1][(nf & 1) * 2 + 1]);
        }
    }

    // ---- positive-tile raw dot dump ----
    int rc = (bi < 16) ? (bi >> 2) : ((bi - 16) >> 2);
    int cc = (bj < 16) ? (bj >> 2) : ((bj - 16) >> 2);
    if (rc == cc) {
        int pidx = (bj < 16) ? (bj & 3) : (4 + ((bj - 16) & 3));
#pragma unroll
        for (int mf = 0; mf < 4; ++mf)
#pragma unroll
            for (int rs = 0; rs < 2; ++rs) {
                int row = bi * 128 + wm * 64 + mf * 16 + gID + rs * 8;
                float* dst = g_pos + (size_t)row * 1024 + pidx * 128;
#pragma unroll
                for (int nf = 0; nf < 4; ++nf) {
                    int col = wn * 32 + nf * 8 + 2 * tig;
                    *(float2*)(dst + col) = make_float2(c[mf][nf][2 * rs], c[mf][nf][2 * rs + 1]);
                }
            }
    }

    // ---- per-row max over this 128-col tile ----
#pragma unroll
    for (int mf = 0; mf < 4; ++mf)
#pragma unroll
        for (int rs = 0; rs < 2; ++rs) {
            int rl = wm * 64 + mf * 16 + gID + rs * 8;
            float mx = -3.4e38f;
#pragma unroll
            for (int nf = 0; nf < 4; ++nf)
                mx = fmaxf(mx, fmaxf(c[mf][nf][2 * rs], c[mf][nf][2 * rs + 1]));
            mx = fmaxf(mx, __shfl_xor_sync(0xffffffffu, mx, 1));
            mx = fmaxf(mx, __shfl_xor_sync(0xffffffffu, mx, 2));
            if (tig == 0) sP[wn][rl] = mx;
        }
    __syncthreads();
    if (t < 128) sM[t] = fmaxf(fmaxf(sP[0][t], sP[1][t]), fmaxf(sP[2][t], sP[3][t]));
    __syncthreads();

    // ---- per-row sum of exp((dot - max)*10) ----
#pragma unroll
    for (int mf = 0; mf < 4; ++mf)
#pragma unroll
        for (int rs = 0; rs < 2; ++rs) {
            int rl = wm * 64 + mf * 16 + gID + rs * 8;
            float M10 = sM[rl] * 10.0f;
            float s = 0.f;
#pragma unroll
            for (int nf = 0; nf < 4; ++nf)
                s += __expf(fmaf(c[mf][nf][2 * rs], 10.0f, -M10))
                   + __expf(fmaf(c[mf][nf][2 * rs + 1], 10.0f, -M10));
            s += __shfl_xor_sync(0xffffffffu, s, 1);
            s += __shfl_xor_sync(0xffffffffu, s, 2);
            if (tig == 0) sP[wn][rl] = s;
        }
    __syncthreads();
    if (t < 128) {
        g_pm[bj][bi * 128 + t] = sM[t] * 10.0f;
        g_ps[bj][bi * 128 + t] = sP[0][t] + sP[1][t] + sP[2][t] + sP[3][t];
    }
}

// ---------------- final per-row loss ----------------
__global__ void __launch_bounds__(128) k_loss() {
    __shared__ float red[128];
    int i = blockIdx.x, t = threadIdx.x;
    int c = (i < NROW) ? (i >> 9) : ((i - NROW) >> 9);

    red[t] = (t < 32) ? g_pm[t][i] : -3.4e38f;
    __syncthreads();
    for (int o = 64; o > 0; o >>= 1) { if (t < o) red[t] = fmaxf(red[t], red[t + o]); __syncthreads(); }
    float M = red[0];
    __syncthreads();

    red[t] = (t < 32) ? g_ps[t][i] * __expf(g_pm[t][i] - M) : 0.f;
    __syncthreads();
    for (int o = 64; o > 0; o >>= 1) { if (t < o) red[t] += red[t + o]; __syncthreads(); }
    float S_all = red[0];
    __syncthreads();

    float lp[8]; int jj[8];
    float sp = 0.f;
#pragma unroll
    for (int u = 0; u < 8; ++u) {
        int qq = t + u * 128;
        int j = (qq < 512) ? c * 512 + qq : NROW + c * 512 + (qq - 512);
        jj[u] = j;
        float d = g_pos[(size_t)i * 1024 + qq];
        lp[u] = fmaf(d, 10.0f, -M);
        if (j != i) sp += __expf(lp[u]);
    }
    red[t] = sp;
    __syncthreads();
    for (int o = 64; o > 0; o >>= 1) { if (t < o) red[t] += red[t + o]; __syncthreads(); }
    float NS = S_all - red[0];
    __syncthreads();

    float ps = 0.f;
#pragma unroll
    for (int u = 0; u < 8; ++u)
        if (jj[u] != i)
            ps += lp[u] - __logf(__expf(lp[u]) + NS + 1e-10f);
    red[t] = ps;
    __syncthreads();
    for (int o = 64; o > 0; o >>= 1) { if (t < o) red[t] += red[t + o]; __syncthreads(); }

    if (t == 0)
        g_rowloss[i] = -(0.1f / 0.07f) * red[0] / (1023.0f + 1e-10f);
}

__global__ void k_reduce(float* __restrict__ out) {
    __shared__ float sh[1024];
    int t = threadIdx.x;
    sh[t] = g_rowloss[t] + g_rowloss[t + 1024] + g_rowloss[t + 2048] + g_rowloss[t + 3072];
    __syncthreads();
    for (int o = 512; o > 0; o >>= 1) { if (t < o) sh[t] += sh[t + o]; __syncthreads(); }
    if (t == 0) out[0] = sh[0] / 4096.0f;
}

// ---------------- launch ----------------
extern "C" void kernel_launch(void* const* d_in, const int* in_sizes, int n_in,
                              void* d_out, int out_size) {
    const float* feats      = (const float*)d_in[0];
    const int*   labels     = (const int*)  d_in[1];
    const float* pixel_q    = (const float*)d_in[2];
    const float* pix_scores = (const float*)d_in[3];
    const float* q_scores   = (const float*)d_in[4];
    float* out = (float*)d_out;

    cudaFuncSetAttribute(k_gemm, cudaFuncAttributeMaxDynamicSharedMemorySize, SMEM_DYN);

    k_zero    <<<(NSEL * NBIN + 255) / 256, 256>>>();
    k_hist    <<<(NPIX + 255) / 256, 256>>>(labels, pix_scores);
    k_qhist   <<<(NCLS * QSZ + 255) / 256, 256>>>(q_scores);
    k_thresh  <<<NSEL, TH_THREADS>>>();
    k_compact <<<(NPIX + 255) / 256, 256>>>(labels, pix_scores);
    k_qcompact<<<(NCLS * QSZ + 255) / 256, 256>>>(q_scores);
    k_ranksel <<<NSEL, 1024>>>();
    k_gather  <<<NANCH, DIMF>>>(feats, pixel_q);
    k_gemm    <<<dim3(32, 32), 256, SMEM_DYN>>>();
    k_loss    <<<NANCH, 128>>>();
    k_reduce  <<<1, 1024>>>(out);
}

// round 6
// speedup vs baseline: 3.7179x; 1.1352x over previous
#include <cuda_runtime.h>
#include <cuda_bf16.h>
#include <cstdint>

#define NCLS    4
#define MAXV    512
#define NROW    2048
#define NANCH   4096
#define DIMF    128
#define NPIX    262144
#define PERBV   131072
#define QSZ     5000
#define NBIN    16384
#define CANDMAX 4096
#define NSEL    8          // 0-3 pixel classes, 4-7 queue classes
#define NTILEPAIRS 528     // 32*33/2

// ---------------- device scratch ----------------
__device__ int                g_hist[NSEL * NBIN];
__device__ int                g_T[NSEL];
__device__ int                g_candCnt[NSEL];
__device__ unsigned long long g_cand[NSEL][CANDMAX];
__device__ int                g_sel[NSEL][MAXV];
__device__ __nv_bfloat16      g_Xhi[NANCH * DIMF];
__device__ __nv_bfloat16      g_Xlo[NANCH * DIMF];
__device__ float              g_pm[32][NANCH];      // per (coltile, row): rowmax*10
__device__ float              g_ps[32][NANCH];      // per (coltile, row): sum exp
__device__ float              g_pos[NANCH * 1024];  // raw positive dots
__device__ float              g_rowloss[NANCH];

// ---------------- helpers ----------------
__device__ __forceinline__ uint32_t smem_u32(const void* p) {
    uint32_t a;
    asm("{ .reg .u64 t; cvta.to.shared.u64 t, %1; cvt.u32.u64 %0, t; }" : "=r"(a) : "l"(p));
    return a;
}
__device__ __forceinline__ void ldsm4(uint32_t* r, uint32_t addr) {
    asm volatile("ldmatrix.sync.aligned.m8n8.x4.shared.b16 {%0,%1,%2,%3}, [%4];"
                 : "=r"(r[0]), "=r"(r[1]), "=r"(r[2]), "=r"(r[3]) : "r"(addr));
}
__device__ __forceinline__ void mma_bf16(float* c, const uint32_t* a, uint32_t b0, uint32_t b1) {
    asm volatile("mma.sync.aligned.m16n8k16.row.col.f32.bf16.bf16.f32 "
                 "{%0,%1,%2,%3}, {%4,%5,%6,%7}, {%8,%9}, {%0,%1,%2,%3};"
                 : "+f"(c[0]), "+f"(c[1]), "+f"(c[2]), "+f"(c[3])
                 : "r"(a[0]), "r"(a[1]), "r"(a[2]), "r"(a[3]), "r"(b0), "r"(b1));
}
__device__ __forceinline__ int score_bin(float s) {
    int b = (int)(s * 16384.0f);
    b = b < 0 ? 0 : b;
    return b > NBIN - 1 ? NBIN - 1 : b;
}

// ---------------- selection ----------------
__global__ void k_zero() {
    int i = blockIdx.x * blockDim.x + threadIdx.x;
    if (i < NSEL * NBIN) g_hist[i] = 0;
    if (i < NSEL) { g_candCnt[i] = 0; g_T[i] = 0; }
}

__global__ void k_hist(const int* __restrict__ labels, const float* __restrict__ scores) {
    int i = blockIdx.x * blockDim.x + threadIdx.x;
    if (i >= NPIX) return;
    atomicAdd(&g_hist[labels[i] * NBIN + score_bin(scores[i])], 1);
}

__global__ void k_qhist(const float* __restrict__ qs) {
    int i = blockIdx.x * blockDim.x + threadIdx.x;
    if (i >= NCLS * QSZ) return;
    atomicAdd(&g_hist[(4 + i / QSZ) * NBIN + score_bin(qs[i])], 1);
}

// parallel threshold: per class, largest bin b with suffix_inclusive(b) >= MAXV
#define TH_THREADS 512
#define TH_CH      (NBIN / TH_THREADS)   // 32 bins per thread
__global__ void __launch_bounds__(TH_THREADS) k_thresh() {
    extern __shared__ int sh[];          // NBIN ints, staged coalesced
    __shared__ int csum[TH_THREADS];
    int c = blockIdx.x, t = threadIdx.x;
    for (int i = t; i < NBIN; i += TH_THREADS) sh[i] = g_hist[c * NBIN + i];
    __syncthreads();
    int s = 0;
    int* h = &sh[t * TH_CH];
#pragma unroll
    for (int u = 0; u < TH_CH; ++u) s += h[u];
    csum[t] = s;
    __syncthreads();
    for (int o = 1; o < TH_THREADS; o <<= 1) {
        int v = (t + o < TH_THREADS) ? csum[t + o] : 0;
        __syncthreads();
        csum[t] += v;
        __syncthreads();
    }
    int above = (t + 1 < TH_THREADS) ? csum[t + 1] : 0;
    if (above < MAXV && csum[t] >= MAXV) {
        int running = above;
#pragma unroll
        for (int u = TH_CH - 1; u >= 0; --u) {
            running += h[u];
            if (running >= MAXV) { g_T[c] = t * TH_CH + u; break; }
        }
    }
}

__global__ void k_compact(const int* __restrict__ labels, const float* __restrict__ scores) {
    int i = blockIdx.x * blockDim.x + threadIdx.x;
    if (i >= NPIX) return;
    int c = labels[i];
    float s = scores[i];
    if (score_bin(s) >= g_T[c]) {
        int pos = atomicAdd(&g_candCnt[c], 1);
        if (pos < CANDMAX)
            g_cand[c][pos] = ((unsigned long long)__float_as_uint(s) << 32)
                           | (unsigned int)(~(unsigned int)i);
    }
}

__global__ void k_qcompact(const float* __restrict__ qs) {
    int i = blockIdx.x * blockDim.x + threadIdx.x;
    if (i >= NCLS * QSZ) return;
    int c = 4 + i / QSZ;
    int id = i % QSZ;
    float s = qs[i];
    if (score_bin(s) >= g_T[c]) {
        int pos = atomicAdd(&g_candCnt[c], 1);
        if (pos < CANDMAX)
            g_cand[c][pos] = ((unsigned long long)__float_as_uint(s) << 32)
                           | (unsigned int)(~(unsigned int)id);
    }
}

__global__ void k_ranksel() {
    __shared__ unsigned long long sk[CANDMAX];
    int c = blockIdx.x;
    int n = g_candCnt[c];
    if (n > CANDMAX) n = CANDMAX;
    for (int i = threadIdx.x; i < n; i += blockDim.x) sk[i] = g_cand[c][i];
    __syncthreads();
    for (int i = threadIdx.x; i < n; i += blockDim.x) {
        unsigned long long k = sk[i];
        int rank = 0;
        for (int j = 0; j < n; ++j) rank += (sk[j] > k);
        if (rank < MAXV)
            g_sel[c][rank] = (int)(~(unsigned int)(k & 0xFFFFFFFFull));
    }
}

// ---------------- gather + split to bf16 hi/lo ----------------
__global__ void k_gather(const float* __restrict__ feats, const float* __restrict__ pq) {
    int r = blockIdx.x;
    int k = threadIdx.x;   // 0..127
    float v;
    if (r < NROW) {
        int c = r >> 9, slot = r & 511;
        int p  = g_sel[c][slot];
        int bv = p >> 17;
        int off = p & (PERBV - 1);
        v = feats[(size_t)bv * DIMF * PERBV + (size_t)k * PERBV + off];
    } else {
        int rr = r - NROW;
        int c = rr >> 9, slot = rr & 511;
        int q = g_sel[4 + c][slot];
        v = pq[((size_t)c * QSZ + q) * DIMF + k];
    }
    __nv_bfloat16 hi = __float2bfloat16(v);
    __nv_bfloat16 lo = __float2bfloat16(v - __bfloat162float(hi));
    g_Xhi[r * DIMF + k] = hi;
    g_Xlo[r * DIMF + k] = lo;
}

// ---------------- fused symmetric GEMM + softmax partials ----------------
// 528 blocks over unordered tile pairs (bi <= bj). One 3-term split-bf16 MMA
// per pair; emits row-partials (rows of bi over cols of bj) and, for bi<bj,
// column-partials (rows of bj over cols of bi) from the same accumulators.
// Same-class tiles dump raw dots to g_pos (plus transposed via smem staging).
#define SMEM_DYN (4 * 32768)
__global__ void __launch_bounds__(256, 1) k_gemm() {
    extern __shared__ char dsm[];
    __shared__ float sP[4][128];
    __shared__ float sM[128];
    int t = threadIdx.x, lane = t & 31, w = t >> 5;
    int wm = w & 1, wn = w >> 1;               // warp tile 64(m) x 32(n)
    int gID = lane >> 2, tig = lane & 3;

    // triangular decode: block L -> (bi, bj), bj >= bi
    int L = blockIdx.x, bi = 0;
    while (L >= 32 - bi) { L -= 32 - bi; ++bi; }
    int bj = bi + L;
    uint32_t sbase = smem_u32(dsm);

    // ---- load 4 tiles to swizzled smem ----
    const __nv_bfloat16* srcs[4] = {
        g_Xhi + (size_t)bi * 128 * DIMF, g_Xlo + (size_t)bi * 128 * DIMF,
        g_Xhi + (size_t)bj * 128 * DIMF, g_Xlo + (size_t)bj * 128 * DIMF };
#pragma unroll
    for (int tl = 0; tl < 4; ++tl) {
        const uint4* src = (const uint4*)srcs[tl];
        char* dst = dsm + tl * 32768;
#pragma unroll
        for (int it = 0; it < 8; ++it) {
            int idx = t + it * 256;            // 2048 chunks of 16B
            int row = idx >> 4, ch = idx & 15;
            uint4 v = src[idx];
            *(uint4*)(dst + row * 256 + ((ch ^ (row & 7)) << 4)) = v;
        }
    }
    __syncthreads();

    // ---- mma mainloop ----
    float c[4][4][4];
#pragma unroll
    for (int mf = 0; mf < 4; ++mf)
#pragma unroll
        for (int nf = 0; nf < 4; ++nf)
#pragma unroll
            for (int u = 0; u < 4; ++u) c[mf][nf][u] = 0.f;

    int q = lane >> 3, rowin = lane & 7;
    int rA_in = rowin + (q & 1) * 8;
    int rB_in = rowin + (q >> 1) * 8;
    int cA_add = q >> 1, cB_add = q & 1;

#pragma unroll
    for (int term = 0; term < 3; ++term) {
        uint32_t Ab = sbase + (term == 2 ? 32768 : 0);
        uint32_t Bb = sbase + (term == 1 ? 98304 : 65536);
#pragma unroll
        for (int k0 = 0; k0 < 8; ++k0) {
            uint32_t a[4][4];
#pragma unroll
            for (int mf = 0; mf < 4; ++mf) {
                int row = wm * 64 + mf * 16 + rA_in;
                int ch = 2 * k0 + cA_add;
                ldsm4(a[mf], Ab + row * 256 + ((ch ^ (row & 7)) << 4));
            }
            uint32_t b[2][4];
#pragma unroll
            for (int nf2 = 0; nf2 < 2; ++nf2) {
                int row = wn * 32 + nf2 * 16 + rB_in;
                int ch = 2 * k0 + cB_add;
                ldsm4(b[nf2], Bb + row * 256 + ((ch ^ (row & 7)) << 4));
            }
#pragma unroll
            for (int mf = 0; mf < 4; ++mf)
#pragma unroll
                for (int nf = 0; nf < 4; ++nf)
                    mma_bf16(c[mf][nf], a[mf], b[nf >> 1][(nf & 1) * 2], b[nf >> 1][(nf & 1) * 2 + 1]);
        }
    }

    int sameclass;
    {
        int rc = (bi < 16) ? (bi >> 2) : ((bi - 16) >> 2);
        int cc = (bj < 16) ? (bj >> 2) : ((bj - 16) >> 2);
        sameclass = (rc == cc);
    }

    // ---- row path: partials for rows of bi over cols of bj ----
#pragma unroll
    for (int mf = 0; mf < 4; ++mf)
#pragma unroll
        for (int rs = 0; rs < 2; ++rs) {
            int rl = wm * 64 + mf * 16 + gID + rs * 8;
            float mx = -3.4e38f;
#pragma unroll
            for (int nf = 0; nf < 4; ++nf)
                mx = fmaxf(mx, fmaxf(c[mf][nf][2 * rs], c[mf][nf][2 * rs + 1]));
            mx = fmaxf(mx, __shfl_xor_sync(0xffffffffu, mx, 1));
            mx = fmaxf(mx, __shfl_xor_sync(0xffffffffu, mx, 2));
            if (tig == 0) sP[wn][rl] = mx;
        }
    __syncthreads();
    if (t < 128) sM[t] = fmaxf(fmaxf(sP[0][t], sP[1][t]), fmaxf(sP[2][t], sP[3][t]));
    __syncthreads();
#pragma unroll
    for (int mf = 0; mf < 4; ++mf)
#pragma unroll
        for (int rs = 0; rs < 2; ++rs) {
            int rl = wm * 64 + mf * 16 + gID + rs * 8;
            float M10 = sM[rl] * 10.0f;
            float s = 0.f;
#pragma unroll
            for (int nf = 0; nf < 4; ++nf)
                s += __expf(fmaf(c[mf][nf][2 * rs], 10.0f, -M10))
                   + __expf(fmaf(c[mf][nf][2 * rs + 1], 10.0f, -M10));
            s += __shfl_xor_sync(0xffffffffu, s, 1);
            s += __shfl_xor_sync(0xffffffffu, s, 2);
            if (tig == 0) sP[wn][rl] = s;
        }
    __syncthreads();
    if (t < 128) {
        g_pm[bj][bi * 128 + t] = sM[t] * 10.0f;
        g_ps[bj][bi * 128 + t] = sP[0][t] + sP[1][t] + sP[2][t] + sP[3][t];
    }
    __syncthreads();

    // ---- column path: partials for rows of bj over cols of bi (bi<bj) ----
    if (bj > bi) {
#pragma unroll
        for (int nf = 0; nf < 4; ++nf)
#pragma unroll
            for (int v = 0; v < 2; ++v) {
                float mx = -3.4e38f;
#pragma unroll
                for (int mf = 0; mf < 4; ++mf)
                    mx = fmaxf(mx, fmaxf(c[mf][nf][v], c[mf][nf][2 + v]));
                mx = fmaxf(mx, __shfl_xor_sync(0xffffffffu, mx, 4));
                mx = fmaxf(mx, __shfl_xor_sync(0xffffffffu, mx, 8));
                mx = fmaxf(mx, __shfl_xor_sync(0xffffffffu, mx, 16));
                int cl = wn * 32 + nf * 8 + 2 * tig + v;
                if (gID == 0) sP[wm][cl] = mx;
            }
        __syncthreads();
        if (t < 128) sM[t] = fmaxf(sP[0][t], sP[1][t]);
        __syncthreads();
#pragma unroll
        for (int nf = 0; nf < 4; ++nf)
#pragma unroll
            for (int v = 0; v < 2; ++v) {
                int cl = wn * 32 + nf * 8 + 2 * tig + v;
                float M10 = sM[cl] * 10.0f;
                float s = 0.f;
#pragma unroll
                for (int mf = 0; mf < 4; ++mf)
                    s += __expf(fmaf(c[mf][nf][v], 10.0f, -M10))
                       + __expf(fmaf(c[mf][nf][2 + v], 10.0f, -M10));
                s += __shfl_xor_sync(0xffffffffu, s, 4);
                s += __shfl_xor_sync(0xffffffffu, s, 8);
                s += __shfl_xor_sync(0xffffffffu, s, 16);
                if (gID == 0) sP[wm][cl] = s;
            }
        __syncthreads();
        if (t < 128) {
            g_pm[bi][bj * 128 + t] = sM[t] * 10.0f;
            g_ps[bi][bj * 128 + t] = sP[0][t] + sP[1][t];
        }
    }

    // ---- positive dumps ----
    if (sameclass) {
        int pidx = (bj < 16) ? (bj & 3) : (4 + (bj & 3));
#pragma unroll
        for (int mf = 0; mf < 4; ++mf)
#pragma unroll
            for (int rs = 0; rs < 2; ++rs) {
                int row = bi * 128 + wm * 64 + mf * 16 + gID + rs * 8;
                float* dst = g_pos + (size_t)row * 1024 + pidx * 128;
#pragma unroll
                for (int nf = 0; nf < 4; ++nf) {
                    int col = wn * 32 + nf * 8 + 2 * tig;
                    *(float2*)(dst + col) = make_float2(c[mf][nf][2 * rs], c[mf][nf][2 * rs + 1]);
                }
            }
        if (bj > bi) {
            // transposed dump for rows of bj, staged through smem for coalescing
            float* smT = (float*)dsm;      // [128][132] floats
            __syncthreads();
#pragma unroll
            for (int mf = 0; mf < 4; ++mf)
#pragma unroll
                for (int nf = 0; nf < 4; ++nf)
#pragma unroll
                    for (int u = 0; u < 4; ++u) {
                        int row = wm * 64 + mf * 16 + gID + (u >> 1) * 8;
                        int col = wn * 32 + nf * 8 + 2 * tig + (u & 1);
                        smT[col * 132 + row] = c[mf][nf][u];
                    }
            __syncthreads();
            int pidxT = (bi < 16) ? (bi & 3) : (4 + (bi & 3));
#pragma unroll
            for (int it = 0; it < 16; ++it) {
                int idx = t + it * 256;        // 4096 float4 chunks
                int r2 = idx >> 5, q4 = idx & 31;
                float4 v = *(float4*)&smT[r2 * 132 + q4 * 4];
                *(float4*)&g_pos[(size_t)(bj * 128 + r2) * 1024 + pidxT * 128 + q4 * 4] = v;
            }
        }
    }
}

// ---------------- final per-row loss ----------------
__global__ void __launch_bounds__(128) k_loss() {
    __shared__ float red[128];
    int i = blockIdx.x, t = threadIdx.x;
    int c = (i < NROW) ? (i >> 9) : ((i - NROW) >> 9);

    red[t] = (t < 32) ? g_pm[t][i] : -3.4e38f;
    __syncthreads();
    for (int o = 64; o > 0; o >>= 1) { if (t < o) red[t] = fmaxf(red[t], red[t + o]); __syncthreads(); }
    float M = red[0];
    __syncthreads();

    red[t] = (t < 32) ? g_ps[t][i] * __expf(g_pm[t][i] - M) : 0.f;
    __syncthreads();
    for (int o = 64; o > 0; o >>= 1) { if (t < o) red[t] += red[t + o]; __syncthreads(); }
    float S_all = red[0];
    __syncthreads();

    float lp[8]; int jj[8];
    float sp = 0.f;
#pragma unroll
    for (int u = 0; u < 8; ++u) {
        int qq = t + u * 128;
        int j = (qq < 512) ? c * 512 + qq : NROW + c * 512 + (qq - 512);
        jj[u] = j;
        float d = g_pos[(size_t)i * 1024 + qq];
        lp[u] = fmaf(d, 10.0f, -M);
        if (j != i) sp += __expf(lp[u]);
    }
    red[t] = sp;
    __syncthreads();
    for (int o = 64; o > 0; o >>= 1) { if (t < o) red[t] += red[t + o]; __syncthreads(); }
    float NS = S_all - red[0];
    __syncthreads();

    float ps = 0.f;
#pragma unroll
    for (int u = 0; u < 8; ++u)
        if (jj[u] != i)
            ps += lp[u] - __logf(__expf(lp[u]) + NS + 1e-10f);
    red[t] = ps;
    __syncthreads();
    for (int o = 64; o > 0; o >>= 1) { if (t < o) red[t] += red[t + o]; __syncthreads(); }

    if (t == 0)
        g_rowloss[i] = -(0.1f / 0.07f) * red[0] / (1023.0f + 1e-10f);
}

__global__ void k_reduce(float* __restrict__ out) {
    __shared__ float sh[1024];
    int t = threadIdx.x;
    sh[t] = g_rowloss[t] + g_rowloss[t + 1024] + g_rowloss[t + 2048] + g_rowloss[t + 3072];
    __syncthreads();
    for (int o = 512; o > 0; o >>= 1) { if (t < o) sh[t] += sh[t + o]; __syncthreads(); }
    if (t == 0) out[0] = sh[0] / 4096.0f;
}

// ---------------- launch ----------------
extern "C" void kernel_launch(void* const* d_in, const int* in_sizes, int n_in,
                              void* d_out, int out_size) {
    const float* feats      = (const float*)d_in[0];
    const int*   labels     = (const int*)  d_in[1];
    const float* pixel_q    = (const float*)d_in[2];
    const float* pix_scores = (const float*)d_in[3];
    const float* q_scores   = (const float*)d_in[4];
    float* out = (float*)d_out;

    cudaFuncSetAttribute(k_gemm,   cudaFuncAttributeMaxDynamicSharedMemorySize, SMEM_DYN);
    cudaFuncSetAttribute(k_thresh, cudaFuncAttributeMaxDynamicSharedMemorySize, NBIN * 4);

    k_zero    <<<(NSEL * NBIN + 255) / 256, 256>>>();
    k_hist    <<<(NPIX + 255) / 256, 256>>>(labels, pix_scores);
    k_qhist   <<<(NCLS * QSZ + 255) / 256, 256>>>(q_scores);
    k_thresh  <<<NSEL, TH_THREADS, NBIN * 4>>>();
    k_compact <<<(NPIX + 255) / 256, 256>>>(labels, pix_scores);
    k_qcompact<<<(NCLS * QSZ + 255) / 256, 256>>>(q_scores);
    k_ranksel <<<NSEL, 1024>>>();
    k_gather  <<<NANCH, DIMF>>>(feats, pixel_q);
    k_gemm    <<<NTILEPAIRS, 256, SMEM_DYN>>>();
    k_loss    <<<NANCH, 128>>>();
    k_reduce  <<<1, 1024>>>(out);
}